// round 13
// baseline (speedup 1.0000x reference)
#include <cuda_runtime.h>
#include <cuda_bf16.h>

#define L_STEPS 256
#define CHUNK   16
#define NCHUNK  (L_STEPS / CHUNK)      // 16
#define THREADS 128
#define ROWQ    (L_STEPS / 4)          // 64 float4 per output row
#define NEG_INV_LN2 (-1.44269504088896340736f)

// Log-domain recurrence, lam folded into the exponent:
//   u = 1-D,  m = (beta-1)*log2(u) + log2(lam)  =>  x = 2^m = lam*u^(beta-1)
//   u' = u*(1-x)                                     (exact)
//   m' = m + cbm*x*(1 + x/2 + x^2/3),  cbm = -(beta-1)/ln2   (x <= ~0.005)
// lam=0 -> m=-inf, ex2(-inf)=+0, D=0 exactly. beta=1 -> cbm=0, exact.
// Reference clamps never fire (u >= 0.995^256 ~= 0.28 >> 1e-12).

__device__ __forceinline__ float4 step4(float& u, float& m, float cbm) {
    float4 v;
    #pragma unroll
    for (int j = 0; j < 4; ++j) {
        float x;
        asm("ex2.approx.f32 %0, %1;" : "=f"(x) : "f"(m));
        float poly = fmaf(x, fmaf(x, 0.33333333f, 0.5f), 1.0f);
        m = fmaf(cbm * x, poly, m);
        u = fmaf(-x, u, u);
        float D = 1.0f - u;
        if (j == 0) v.x = D; else if (j == 1) v.y = D;
        else if (j == 2) v.z = D; else v.w = D;
    }
    return v;
}

// Swizzled tile: logical (row r, group g) lives at tile4[buf][r][g ^ ((r>>1)&3)].
// Bank-group = (4r + slot) mod 8; per 8-lane LSU phase this takes all 8 values
// on both the write side (r = tid) and the read side (2 rows x 4 groups):
// conflict-free STS.128 / LDS.128.

__global__ __launch_bounds__(THREADS, 12) void ductile_kernel(
    const float2* __restrict__ model_out,
    float4* __restrict__ out)
{
    __shared__ float4 tile4[2][THREADS][4];   // 2 x 8 KB

    const int tid = threadIdx.x;
    const int b0  = blockIdx.x * THREADS;

    float2 mo = model_out[b0 + tid];
    const float lam = 0.001f * fmaxf(mo.x, 0.0f);
    const float bm1 = 10.0f * fmaxf(mo.y, 0.0f);
    const float cbm = NEG_INV_LN2 * bm1;

    float u = 1.0f;
    float m = __log2f(lam);                  // -inf when lam == 0

    float4* orow = out + (size_t)b0 * ROWQ;
    const int sw = (tid >> 1) & 3;

    // ---- prologue: compute chunk 0
    #pragma unroll
    for (int g = 0; g < 4; ++g)
        tile4[0][tid][g ^ sw] = step4(u, m, cbm);
    __syncthreads();

    // ---- steady state: store chunk ch-1 while computing chunk ch
    #pragma unroll 1
    for (int ch = 1; ch < NCHUNK; ++ch) {
        const float4 (*src)[4] = tile4[(ch - 1) & 1];
        float4 (*dst)[4] = tile4[ch & 1];
        float4* og = orow + (ch - 1) * 4;

        #pragma unroll
        for (int p = 0; p < 4; ++p) {
            int idx = p * THREADS + tid;
            int r   = idx >> 2;              // 0..127
            int c4  = idx & 3;               // 0..3
            float4 sv = src[r][c4 ^ ((r >> 1) & 3)];
            __stcs(&og[r * ROWQ + c4], sv);
            dst[tid][p ^ sw] = step4(u, m, cbm);
        }
        __syncthreads();
    }

    // ---- epilogue: store chunk NCHUNK-1
    {
        const float4 (*src)[4] = tile4[(NCHUNK - 1) & 1];
        float4* og = orow + (NCHUNK - 1) * 4;
        #pragma unroll
        for (int p = 0; p < 4; ++p) {
            int idx = p * THREADS + tid;
            int r   = idx >> 2;
            int c4  = idx & 3;
            float4 sv = src[r][c4 ^ ((r >> 1) & 3)];
            __stcs(&og[r * ROWQ + c4], sv);
        }
    }
}

extern "C" void kernel_launch(void* const* d_in, const int* in_sizes, int n_in,
                              void* d_out, int out_size)
{
    const float2* model_out = (const float2*)d_in[0];
    float4* out = (float4*)d_out;
    int B = in_sizes[0] / 2;                 // 262144

    int blocks = B / THREADS;                // 2048, exact
    ductile_kernel<<<blocks, THREADS>>>(model_out, out);
}